// round 15
// baseline (speedup 1.0000x reference)
#include <cuda_runtime.h>
#include <cuda_bf16.h>
#include <cstdint>

// Causal linear attention (elu+1), persistent fused kernel (chunk KV aggregate
// + decoupled-lookback prefix + intra-chunk attention), mma.sync bf16 hi/lo.
// q,k,v: [B=4, L=2048, H=16, D=64] fp32 -> out [B,L,H,64] fp32.
// R13: co-resident blocks de-phased (section order by blk parity).
// R14: Ksum folded into P0; redundant __threadfence removed.
// R15: persistent blocks + atomic work-stealing (kills wave-quantization tail).

namespace {
constexpr int B_ = 4, L_ = 2048, H_ = 16, D_ = 64, M_ = 64;
constexpr int C_ = 128;
constexpr int NC_ = L_ / C_;   // 16
constexpr int BH_ = B_ * H_;   // 64
constexpr int NBLK_ = BH_ * NC_;  // 1024
constexpr int NPERS_ = 304;       // 2 blocks/SM on 152-SM GB300
constexpr float EPS_ = 1e-6f;
constexpr int HD_ = H_ * D_;   // 1024
constexpr int PS_ = 72;        // padded row stride (bf16) -> 144B, conflict-free LDSM

constexpr int SZT = C_ * PS_ * 2;   // 18432 B per 128-row bf16 tile
constexpr int SZS = 64 * PS_ * 2;   // 9216 B per 64-row bf16 tile

// smem layout (Q never in smem; loaded straight into A-fragments)
constexpr int OFF_KH = 0;
constexpr int OFF_KL = OFF_KH + SZT;
constexpr int OFF_VH = OFF_KL + SZT;
constexpr int OFF_VL = OFF_VH + SZT;          // K/V tiles: 73728 B
constexpr int OFF_SH = 4 * SZT;               // S hi tile (9216B)
constexpr int OFF_SL = OFF_SH + SZS;          // S lo tile (9216B)
constexpr int OFF_RED = OFF_SL + SZS;         // 16x64 fp32 Ksum partials (4KB)
constexpr int OFF_ST  = OFF_RED + 4096;       // [0]: lookback status, [4]: blk
constexpr int SMEM3   = OFF_ST + 16;          // ~94 KB -> 2 blocks/SM

constexpr int AGG_N = D_ * M_ + D_;           // 4160 floats: KV + Ksum
}

__device__ float g_agg[NBLK_][AGG_N];
__device__ float g_inc[NBLK_][AGG_N];
__device__ int   g_flag[NBLK_];
__device__ int   g_work;

__device__ __forceinline__ float fmap(float x) { return x > 0.f ? x + 1.f : __expf(x); }

__device__ __forceinline__ uint32_t smem_u32(const void* p) {
    uint32_t a;
    asm("{ .reg .u64 t; cvta.to.shared.u64 t, %1; cvt.u32.u64 %0, t; }" : "=r"(a) : "l"(p));
    return a;
}
__device__ __forceinline__ int ld_acquire(const int* p) {
    int v;
    asm volatile("ld.acquire.gpu.global.b32 %0, [%1];" : "=r"(v) : "l"(p) : "memory");
    return v;
}
__device__ __forceinline__ void st_release(int* p, int v) {
    asm volatile("st.release.gpu.global.b32 [%0], %1;" :: "l"(p), "r"(v) : "memory");
}
// truncation-based hi/lo split of a float pair -> packed bf16x2 (lo lane = f0)
__device__ __forceinline__ void tsplit2(float f0, float f1, uint32_t& h, uint32_t& l) {
    const uint32_t u0 = __float_as_uint(f0), u1 = __float_as_uint(f1);
    asm("prmt.b32 %0, %1, %2, 0x7632;" : "=r"(h) : "r"(u0), "r"(u1));
    const float r0 = f0 - __uint_as_float(u0 & 0xffff0000u);
    const float r1 = f1 - __uint_as_float(u1 & 0xffff0000u);
    asm("cvt.rn.bf16x2.f32 %0, %1, %2;" : "=r"(l) : "f"(r1), "f"(r0));
}
__device__ __forceinline__ void tsplit4(const float* f, uint2& hi, uint2& lo) {
    tsplit2(f[0], f[1], hi.x, lo.x);
    tsplit2(f[2], f[3], hi.y, lo.y);
}

__device__ __forceinline__ void ldsm_x4(uint32_t* r, uint32_t addr) {
    asm volatile("ldmatrix.sync.aligned.m8n8.x4.shared.b16 {%0,%1,%2,%3}, [%4];"
                 : "=r"(r[0]), "=r"(r[1]), "=r"(r[2]), "=r"(r[3]) : "r"(addr));
}
__device__ __forceinline__ void ldsm_x4t(uint32_t* r, uint32_t addr) {
    asm volatile("ldmatrix.sync.aligned.m8n8.x4.trans.shared.b16 {%0,%1,%2,%3}, [%4];"
                 : "=r"(r[0]), "=r"(r[1]), "=r"(r[2]), "=r"(r[3]) : "r"(addr));
}
__device__ __forceinline__ void ldsm_x2t(uint32_t& b0, uint32_t& b1, uint32_t addr) {
    asm volatile("ldmatrix.sync.aligned.m8n8.x2.trans.shared.b16 {%0,%1}, [%2];"
                 : "=r"(b0), "=r"(b1) : "r"(addr));
}
__device__ __forceinline__ void mma16816(float* c, const uint32_t* a, uint32_t b0, uint32_t b1) {
    asm("mma.sync.aligned.m16n8k16.row.col.f32.bf16.bf16.f32 "
        "{%0,%1,%2,%3}, {%4,%5,%6,%7}, {%8,%9}, {%0,%1,%2,%3};"
        : "+f"(c[0]), "+f"(c[1]), "+f"(c[2]), "+f"(c[3])
        : "r"(a[0]), "r"(a[1]), "r"(a[2]), "r"(a[3]), "r"(b0), "r"(b1));
}

// ---------------------------------------------------------------------------
__global__ void la_clear() {
    const int i = blockIdx.x * 256 + threadIdx.x;
    if (i < NBLK_) g_flag[i] = 0;
    if (i == 0) g_work = 0;
}

// ---------------------------------------------------------------------------
// Persistent fused kernel. grid = NPERS_, block = 256 (8 warps).
// Chunks (blk = c*64 + bh) grabbed dynamically via atomicAdd.
// ---------------------------------------------------------------------------
__global__ __launch_bounds__(256, 2) void la_fused(const float* __restrict__ q,
                                                   const float* __restrict__ k,
                                                   const float* __restrict__ v,
                                                   float* __restrict__ out) {
    extern __shared__ char smem[];
    const uint32_t sb = smem_u32(smem);
    const int tid = threadIdx.x;
    const int wid = tid >> 5, lane = tid & 31;

    const int rt = (wid < 4) ? wid : 11 - wid;    // SMSP-balanced row-tile
    const int r0 = rt * 16;
    const int g4 = lane >> 2, t4 = lane & 3;

    const int krow = (lane & 7) + ((lane >> 4) & 1) * 8;   // K x4 (phase A)
    const int kcol = ((lane >> 3) & 1) * 8;
    const int vrow = (lane & 7) + ((lane >> 3) & 1) * 8;   // V/S x4t + x2t row
    const int vcol = ((lane >> 4) & 1) * 8;
    const int asrow = (lane & 7) + ((lane >> 4) & 1) * 8;  // K x4t (aggregate MMA)
    const int ascol = ((lane >> 3) & 1) * 8;

    volatile int* stat_s = reinterpret_cast<volatile int*>(smem + OFF_ST);
    volatile int* blk_s  = reinterpret_cast<volatile int*>(smem + OFF_ST + 4);

    while (true) {
        if (tid == 0) *blk_s = atomicAdd(&g_work, 1);
        __syncthreads();
        const int blk = *blk_s;
        if (blk >= NBLK_) return;

        const int c = blk >> 6, bh = blk & 63;
        const int b = bh / H_, h = bh % H_;
        const long gbase = (((long)b * L_ + (long)c * C_) * H_ + h) * D_;

        // ---- qa frags: direct gmem -> register load of Qf (streaming) -------
        uint32_t qa[2][4][4];
        {
            const float* qr0 = q + gbase + (long)(r0 + g4) * HD_;
            const float* qr8 = qr0 + 8 * HD_;
#pragma unroll
            for (int kt = 0; kt < 4; kt++) {
                const int c0 = kt * 16 + 2 * t4;
                const float2 f0 = __ldcs(reinterpret_cast<const float2*>(qr0 + c0));
                const float2 f1 = __ldcs(reinterpret_cast<const float2*>(qr8 + c0));
                const float2 f2 = __ldcs(reinterpret_cast<const float2*>(qr0 + c0 + 8));
                const float2 f3 = __ldcs(reinterpret_cast<const float2*>(qr8 + c0 + 8));
                tsplit2(fmap(f0.x), fmap(f0.y), qa[0][kt][0], qa[1][kt][0]);
                tsplit2(fmap(f1.x), fmap(f1.y), qa[0][kt][1], qa[1][kt][1]);
                tsplit2(fmap(f2.x), fmap(f2.y), qa[0][kt][2], qa[1][kt][2]);
                tsplit2(fmap(f3.x), fmap(f3.y), qa[0][kt][3], qa[1][kt][3]);
            }
        }

        // ---- P0: k,v chunk (streaming); fmap(k); split -> smem tiles;
        //      Ksum partials in registers (each thread's d4 is fixed) ---------
        float ksp[4] = {0.f, 0.f, 0.f, 0.f};
#pragma unroll 4
        for (int it = 0; it < 8; it++) {
            const int i = tid + it * 256;
            const int l = i >> 4, d4 = (i & 15) * 4;
            const long g = gbase + (long)l * HD_ + d4;
            const int so = (l * PS_ + d4) * 2;
            uint2 hi, lo;

            const float4 kv = __ldcs(reinterpret_cast<const float4*>(&k[g]));
            const float4 vv = __ldcs(reinterpret_cast<const float4*>(&v[g]));

            float fk[4] = {fmap(kv.x), fmap(kv.y), fmap(kv.z), fmap(kv.w)};
            ksp[0] += fk[0]; ksp[1] += fk[1]; ksp[2] += fk[2]; ksp[3] += fk[3];
            tsplit4(fk, hi, lo);
            *reinterpret_cast<uint2*>(smem + OFF_KH + so) = hi;
            *reinterpret_cast<uint2*>(smem + OFF_KL + so) = lo;

            float fv[4] = {vv.x, vv.y, vv.z, vv.w};
            tsplit4(fv, hi, lo);
            *reinterpret_cast<uint2*>(smem + OFF_VH + so) = hi;
            *reinterpret_cast<uint2*>(smem + OFF_VL + so) = lo;
        }
        {   // park Ksum partials: red[t][d], t = tid>>4 (l-group)
            float* red = reinterpret_cast<float*>(smem + OFF_RED);
            *reinterpret_cast<float4*>(&red[(tid >> 4) * 64 + (tid & 15) * 4]) =
                make_float4(ksp[0], ksp[1], ksp[2], ksp[3]);
        }
        __syncthreads();

        const int m0r = r0 + g4, m1r = m0r + 8;
        float z0 = 0.f, z1 = 0.f;
        float o[8][4];
#pragma unroll
        for (int nt = 0; nt < 8; nt++)
#pragma unroll
            for (int t = 0; t < 4; t++) o[nt][t] = 0.f;

        // ---- section: chunk KV aggregate + Ksum finish + publish ------------
        auto do_agg = [&]() {
            if (c >= NC_ - 1) return;
            float acc[4][4];
#pragma unroll
            for (int mt = 0; mt < 4; mt++)
#pragma unroll
                for (int t = 0; t < 4; t++) acc[mt][t] = 0.f;

#pragma unroll
            for (int kt = 0; kt < 8; kt++) {
                uint32_t bh0, bh1, bl0, bl1;
                const uint32_t adrV = sb + OFF_VH +
                    (uint32_t)(((kt * 16 + vrow) * PS_ + wid * 8) * 2);
                ldsm_x2t(bh0, bh1, adrV);
                ldsm_x2t(bl0, bl1, adrV + (OFF_VL - OFF_VH));
#pragma unroll
                for (int mt = 0; mt < 4; mt++) {
                    uint32_t ah[4], al[4];
                    const uint32_t adrK = sb + OFF_KH +
                        (uint32_t)(((kt * 16 + asrow) * PS_ + mt * 16 + ascol) * 2);
                    ldsm_x4t(ah, adrK);
                    ldsm_x4t(al, adrK + (OFF_KL - OFF_KH));
                    mma16816(acc[mt], ah, bh0, bh1);
                    mma16816(acc[mt], ah, bl0, bl1);
                    mma16816(acc[mt], al, bh0, bh1);
                }
            }

            const int m = wid * 8 + 2 * t4;
#pragma unroll
            for (int mt = 0; mt < 4; mt++) {
                const int d0 = mt * 16 + g4;
                *reinterpret_cast<float2*>(&g_agg[blk][d0 * M_ + m]) =
                    make_float2(acc[mt][0], acc[mt][1]);
                *reinterpret_cast<float2*>(&g_agg[blk][(d0 + 8) * M_ + m]) =
                    make_float2(acc[mt][2], acc[mt][3]);
            }

            if (tid < 64) {
                const float* red = reinterpret_cast<const float*>(smem + OFF_RED);
                float s = 0.f;
#pragma unroll
                for (int t = 0; t < 16; t++) s += red[t * 64 + tid];
                g_agg[blk][D_ * M_ + tid] = s;
            }
            __syncthreads();
            if (tid == 0) st_release(&g_flag[blk], (c == 0) ? 3 : 1);
        };

        // ---- section: fused phase A+B (intra-chunk) --------------------------
        auto do_ab = [&]() {
            for (int j2 = 0; j2 <= rt; j2++) {
                float acch[2][4] = {{0.f, 0.f, 0.f, 0.f}, {0.f, 0.f, 0.f, 0.f}};
                float accl[2][4] = {{0.f, 0.f, 0.f, 0.f}, {0.f, 0.f, 0.f, 0.f}};
#pragma unroll
                for (int kt = 0; kt < 4; kt++) {
                    uint32_t kh[4], kl[4];
                    const uint32_t adr = sb + OFF_KH +
                        (uint32_t)(((16 * j2 + krow) * PS_ + kt * 16 + kcol) * 2);
                    ldsm_x4(kh, adr);
                    ldsm_x4(kl, adr + (OFF_KL - OFF_KH));
                    mma16816(acch[0], qa[0][kt], kh[0], kh[1]);
                    mma16816(acch[1], qa[0][kt], kh[2], kh[3]);
                    mma16816(accl[0], qa[0][kt], kl[0], kl[1]);
                    mma16816(accl[1], qa[0][kt], kl[2], kl[3]);
                    mma16816(accl[0], qa[1][kt], kh[0], kh[1]);
                    mma16816(accl[1], qa[1][kt], kh[2], kh[3]);
                }

                uint32_t aH[4], aL[4];
#pragma unroll
                for (int tl = 0; tl < 2; tl++) {
                    float c0 = acch[tl][0] + accl[tl][0];
                    float c1 = acch[tl][1] + accl[tl][1];
                    float c2 = acch[tl][2] + accl[tl][2];
                    float c3 = acch[tl][3] + accl[tl][3];
                    if (j2 == rt) {
                        const int n0 = 16 * rt + tl * 8 + 2 * t4;
                        c0 = (n0     <= m0r) ? c0 : 0.f;
                        c1 = (n0 + 1 <= m0r) ? c1 : 0.f;
                        c2 = (n0     <= m1r) ? c2 : 0.f;
                        c3 = (n0 + 1 <= m1r) ? c3 : 0.f;
                    }
                    z0 += c0 + c1;
                    z1 += c2 + c3;
                    tsplit2(c0, c1, aH[tl * 2], aL[tl * 2]);
                    tsplit2(c2, c3, aH[tl * 2 + 1], aL[tl * 2 + 1]);
                }

#pragma unroll
                for (int nt2 = 0; nt2 < 4; nt2++) {
                    uint32_t vh[4], vl[4];
                    const uint32_t adr = sb + OFF_VH +
                        (uint32_t)(((16 * j2 + vrow) * PS_ + nt2 * 16 + vcol) * 2);
                    ldsm_x4t(vh, adr);
                    ldsm_x4t(vl, adr + (OFF_VL - OFF_VH));
                    mma16816(o[2 * nt2],     aH, vh[0], vh[1]);
                    mma16816(o[2 * nt2 + 1], aH, vh[2], vh[3]);
                    mma16816(o[2 * nt2],     aH, vl[0], vl[1]);
                    mma16816(o[2 * nt2 + 1], aH, vl[2], vl[3]);
                    mma16816(o[2 * nt2],     aL, vh[0], vh[1]);
                    mma16816(o[2 * nt2 + 1], aL, vh[2], vh[3]);
                }
            }
            z0 += __shfl_xor_sync(0xffffffffu, z0, 1);
            z0 += __shfl_xor_sync(0xffffffffu, z0, 2);
            z1 += __shfl_xor_sync(0xffffffffu, z1, 1);
            z1 += __shfl_xor_sync(0xffffffffu, z1, 2);
        };

        // ---- de-phase: section order by blk parity ---------------------------
        if ((blk >> 2) & 1) {
            do_ab();
            do_agg();
        } else {
            do_agg();
            do_ab();
        }

        // ---- block-wide lookback + phase C (skipped for c == 0) --------------
        float o9[4] = {0.f, 0.f, 0.f, 0.f};
        if (c > 0) {
            float sp[16];
#pragma unroll
            for (int t = 0; t < 16; t++) sp[t] = 0.f;
            float ksum_prev = 0.f;
            float ksum_own = (c < NC_ - 1 && tid < 64) ? g_agg[blk][D_ * M_ + tid] : 0.f;

            int j = blk - BH_;
            while (true) {
                if (tid == 0) {
                    int s;
                    do { s = ld_acquire(&g_flag[j]); } while (s == 0);
                    *stat_s = s;
                }
                __syncthreads();
                const int s = *stat_s;
                const float* src = (s == 2) ? g_inc[j] : g_agg[j];
#pragma unroll
                for (int ii = 0; ii < 4; ii++) {
                    const float4 t = *reinterpret_cast<const float4*>(&src[4 * (tid + ii * 256)]);
                    sp[ii * 4 + 0] += t.x; sp[ii * 4 + 1] += t.y;
                    sp[ii * 4 + 2] += t.z; sp[ii * 4 + 3] += t.w;
                }
                if (tid < 64) ksum_prev += src[D_ * M_ + tid];
                __syncthreads();
                if (s >= 2) break;
                j -= BH_;
            }

            // publish inclusive (exclusive prefix + own aggregate)
            if (c < NC_ - 1) {
#pragma unroll
                for (int ii = 0; ii < 4; ii++) {
                    const float4 t = *reinterpret_cast<const float4*>(&g_agg[blk][4 * (tid + ii * 256)]);
                    *reinterpret_cast<float4*>(&g_inc[blk][4 * (tid + ii * 256)]) =
                        make_float4(sp[ii * 4 + 0] + t.x, sp[ii * 4 + 1] + t.y,
                                    sp[ii * 4 + 2] + t.z, sp[ii * 4 + 3] + t.w);
                }
                if (tid < 64) g_inc[blk][D_ * M_ + tid] = ksum_prev + ksum_own;
                __syncthreads();
                if (tid == 0) st_release(&g_flag[blk], 2);
            } else {
                __syncthreads();
            }

            // split S_prev -> S smem tiles + Ksum column 64
#pragma unroll
            for (int ii = 0; ii < 4; ii++) {
                const int i = tid + ii * 256;
                const int d = i >> 4, m4 = (i & 15) * 4;
                uint2 hi, lo;
                tsplit4(&sp[ii * 4], hi, lo);
                const int so = (d * PS_ + m4) * 2;
                *reinterpret_cast<uint2*>(smem + OFF_SH + so) = hi;
                *reinterpret_cast<uint2*>(smem + OFF_SL + so) = lo;
            }
            if (tid < D_) {
                uint32_t hh, ll;
                tsplit2(ksum_prev, 0.f, hh, ll);
                const int so = (tid * PS_ + 64) * 2;
                *reinterpret_cast<uint2*>(smem + OFF_SH + so) = make_uint2(hh, 0u);
                *reinterpret_cast<uint2*>(smem + OFF_SH + so + 8) = make_uint2(0u, 0u);
                *reinterpret_cast<uint2*>(smem + OFF_SL + so) = make_uint2(ll, 0u);
                *reinterpret_cast<uint2*>(smem + OFF_SL + so + 8) = make_uint2(0u, 0u);
            }
            __syncthreads();

            // phase C: O += Qf S_prev (+ 9th n-tile -> qdk)
#pragma unroll
            for (int kt = 0; kt < 4; kt++) {
#pragma unroll
                for (int nt2 = 0; nt2 < 4; nt2++) {
                    uint32_t vh[4], vl[4];
                    const uint32_t adr = sb + OFF_SH +
                        (uint32_t)(((kt * 16 + vrow) * PS_ + nt2 * 16 + vcol) * 2);
                    ldsm_x4t(vh, adr);
                    ldsm_x4t(vl, adr + (OFF_SL - OFF_SH));
                    mma16816(o[2 * nt2],     qa[0][kt], vh[0], vh[1]);
                    mma16816(o[2 * nt2 + 1], qa[0][kt], vh[2], vh[3]);
                    mma16816(o[2 * nt2],     qa[0][kt], vl[0], vl[1]);
                    mma16816(o[2 * nt2 + 1], qa[0][kt], vl[2], vl[3]);
                    mma16816(o[2 * nt2],     qa[1][kt], vh[0], vh[1]);
                    mma16816(o[2 * nt2 + 1], qa[1][kt], vh[2], vh[3]);
                }
                {
                    uint32_t bh0, bh1, bl0, bl1;
                    const uint32_t adr = sb + OFF_SH +
                        (uint32_t)(((kt * 16 + vrow) * PS_ + 64) * 2);
                    ldsm_x2t(bh0, bh1, adr);
                    ldsm_x2t(bl0, bl1, adr + (OFF_SL - OFF_SH));
                    mma16816(o9, qa[0][kt], bh0, bh1);
                    mma16816(o9, qa[0][kt], bl0, bl1);
                    mma16816(o9, qa[1][kt], bh0, bh1);
                }
            }
        }

        // ---- epilogue: z = rowsum(A) + Qf.Ksum_prev; divide, store -----------
        {
            const float qdk_a = __shfl_sync(0xffffffffu, o9[0], g4 * 4);
            const float qdk_b = __shfl_sync(0xffffffffu, o9[2], g4 * 4);
            const float inva = 1.f / (z0 + qdk_a + EPS_);
            const float invb = 1.f / (z1 + qdk_b + EPS_);
            const long ob0 = gbase + (long)m0r * HD_;
            const long ob1 = gbase + (long)m1r * HD_;
#pragma unroll
            for (int nt = 0; nt < 8; nt++) {
                const int n = nt * 8 + 2 * t4;
                __stcs(reinterpret_cast<float2*>(&out[ob0 + n]),
                       make_float2(o[nt][0] * inva, o[nt][1] * inva));
                __stcs(reinterpret_cast<float2*>(&out[ob1 + n]),
                       make_float2(o[nt][2] * invb, o[nt][3] * invb));
            }
        }

        __syncthreads();   // keep warps converged; smem safe for next iteration
    }
}

// ---------------------------------------------------------------------------
extern "C" void kernel_launch(void* const* d_in, const int* in_sizes, int n_in,
                              void* d_out, int out_size) {
    const float* q = (const float*)d_in[0];
    const float* k = (const float*)d_in[1];
    const float* v = (const float*)d_in[2];
    float* out = (float*)d_out;

    cudaFuncSetAttribute(la_fused, cudaFuncAttributeMaxDynamicSharedMemorySize, SMEM3);

    la_clear<<<(NBLK_ + 255) / 256, 256>>>();
    la_fused<<<NPERS_, 256, SMEM3>>>(q, k, v, out);
}

// round 16
// speedup vs baseline: 1.1508x; 1.1508x over previous
#include <cuda_runtime.h>
#include <cuda_bf16.h>
#include <cstdint>

// Causal linear attention (elu+1), SINGLE fused kernel (chunk KV aggregate +
// decoupled-lookback prefix + intra-chunk attention), mma.sync bf16 hi/lo.
// q,k,v: [B=4, L=2048, H=16, D=64] fp32 -> out [B,L,H,64] fp32.
// R13: co-resident blocks de-phased (section order by blk parity).
// R14: Ksum folded into P0; redundant __threadfence removed.
// R16: V-fragment LDSM for nt2=0 hoisted above the A-conversion block
//      (hides LDS latency under mask/rowsum/split ALU work).

namespace {
constexpr int B_ = 4, L_ = 2048, H_ = 16, D_ = 64, M_ = 64;
constexpr int C_ = 128;
constexpr int NC_ = L_ / C_;   // 16
constexpr int BH_ = B_ * H_;   // 64
constexpr int NBLK_ = BH_ * NC_;  // 1024
constexpr float EPS_ = 1e-6f;
constexpr int HD_ = H_ * D_;   // 1024
constexpr int PS_ = 72;        // padded row stride (bf16) -> 144B, conflict-free LDSM

constexpr int SZT = C_ * PS_ * 2;   // 18432 B per 128-row bf16 tile
constexpr int SZS = 64 * PS_ * 2;   // 9216 B per 64-row bf16 tile

// smem layout (Q never in smem; loaded straight into A-fragments)
constexpr int OFF_KH = 0;
constexpr int OFF_KL = OFF_KH + SZT;
constexpr int OFF_VH = OFF_KL + SZT;
constexpr int OFF_VL = OFF_VH + SZT;          // K/V tiles: 73728 B
constexpr int OFF_SH = 4 * SZT;               // S hi tile (9216B)
constexpr int OFF_SL = OFF_SH + SZS;          // S lo tile (9216B)
constexpr int OFF_RED = OFF_SL + SZS;         // 16x64 fp32 Ksum partials (4KB)
constexpr int OFF_ST  = OFF_RED + 4096;       // lookback status word
constexpr int SMEM3   = OFF_ST + 16;          // ~94 KB -> 2 blocks/SM

constexpr int AGG_N = D_ * M_ + D_;           // 4160 floats: KV + Ksum
}

__device__ float g_agg[NBLK_][AGG_N];
__device__ float g_inc[NBLK_][AGG_N];
__device__ int   g_flag[NBLK_];

__device__ __forceinline__ float fmap(float x) { return x > 0.f ? x + 1.f : __expf(x); }

__device__ __forceinline__ uint32_t smem_u32(const void* p) {
    uint32_t a;
    asm("{ .reg .u64 t; cvta.to.shared.u64 t, %1; cvt.u32.u64 %0, t; }" : "=r"(a) : "l"(p));
    return a;
}
__device__ __forceinline__ int ld_acquire(const int* p) {
    int v;
    asm volatile("ld.acquire.gpu.global.b32 %0, [%1];" : "=r"(v) : "l"(p) : "memory");
    return v;
}
__device__ __forceinline__ void st_release(int* p, int v) {
    asm volatile("st.release.gpu.global.b32 [%0], %1;" :: "l"(p), "r"(v) : "memory");
}
// truncation-based hi/lo split of a float pair -> packed bf16x2 (lo lane = f0)
__device__ __forceinline__ void tsplit2(float f0, float f1, uint32_t& h, uint32_t& l) {
    const uint32_t u0 = __float_as_uint(f0), u1 = __float_as_uint(f1);
    asm("prmt.b32 %0, %1, %2, 0x7632;" : "=r"(h) : "r"(u0), "r"(u1));
    const float r0 = f0 - __uint_as_float(u0 & 0xffff0000u);
    const float r1 = f1 - __uint_as_float(u1 & 0xffff0000u);
    asm("cvt.rn.bf16x2.f32 %0, %1, %2;" : "=r"(l) : "f"(r1), "f"(r0));
}
__device__ __forceinline__ void tsplit4(const float* f, uint2& hi, uint2& lo) {
    tsplit2(f[0], f[1], hi.x, lo.x);
    tsplit2(f[2], f[3], hi.y, lo.y);
}

__device__ __forceinline__ void ldsm_x4(uint32_t* r, uint32_t addr) {
    asm volatile("ldmatrix.sync.aligned.m8n8.x4.shared.b16 {%0,%1,%2,%3}, [%4];"
                 : "=r"(r[0]), "=r"(r[1]), "=r"(r[2]), "=r"(r[3]) : "r"(addr));
}
__device__ __forceinline__ void ldsm_x4t(uint32_t* r, uint32_t addr) {
    asm volatile("ldmatrix.sync.aligned.m8n8.x4.trans.shared.b16 {%0,%1,%2,%3}, [%4];"
                 : "=r"(r[0]), "=r"(r[1]), "=r"(r[2]), "=r"(r[3]) : "r"(addr));
}
__device__ __forceinline__ void ldsm_x2t(uint32_t& b0, uint32_t& b1, uint32_t addr) {
    asm volatile("ldmatrix.sync.aligned.m8n8.x2.trans.shared.b16 {%0,%1}, [%2];"
                 : "=r"(b0), "=r"(b1) : "r"(addr));
}
__device__ __forceinline__ void mma16816(float* c, const uint32_t* a, uint32_t b0, uint32_t b1) {
    asm("mma.sync.aligned.m16n8k16.row.col.f32.bf16.bf16.f32 "
        "{%0,%1,%2,%3}, {%4,%5,%6,%7}, {%8,%9}, {%0,%1,%2,%3};"
        : "+f"(c[0]), "+f"(c[1]), "+f"(c[2]), "+f"(c[3])
        : "r"(a[0]), "r"(a[1]), "r"(a[2]), "r"(a[3]), "r"(b0), "r"(b1));
}

// ---------------------------------------------------------------------------
__global__ void la_clear() {
    const int i = blockIdx.x * 256 + threadIdx.x;
    if (i < NBLK_) g_flag[i] = 0;
}

// ---------------------------------------------------------------------------
// Fused kernel. grid = NBLK_ (blk = c*64 + bh), block = 256 (8 warps).
// ---------------------------------------------------------------------------
__global__ __launch_bounds__(256, 2) void la_fused(const float* __restrict__ q,
                                                   const float* __restrict__ k,
                                                   const float* __restrict__ v,
                                                   float* __restrict__ out) {
    extern __shared__ char smem[];
    const uint32_t sb = smem_u32(smem);
    const int tid = threadIdx.x;
    const int wid = tid >> 5, lane = tid & 31;

    const int blk = blockIdx.x;
    const int c = blk >> 6, bh = blk & 63;
    const int b = bh / H_, h = bh % H_;
    const long gbase = (((long)b * L_ + (long)c * C_) * H_ + h) * D_;

    const int rt = (wid < 4) ? wid : 11 - wid;    // SMSP-balanced row-tile
    const int r0 = rt * 16;
    const int g4 = lane >> 2, t4 = lane & 3;

    // ---- qa frags: direct gmem -> register load of Qf (no smem, streaming) --
    uint32_t qa[2][4][4];
    {
        const float* qr0 = q + gbase + (long)(r0 + g4) * HD_;
        const float* qr8 = qr0 + 8 * HD_;
#pragma unroll
        for (int kt = 0; kt < 4; kt++) {
            const int c0 = kt * 16 + 2 * t4;
            const float2 f0 = __ldcs(reinterpret_cast<const float2*>(qr0 + c0));
            const float2 f1 = __ldcs(reinterpret_cast<const float2*>(qr8 + c0));
            const float2 f2 = __ldcs(reinterpret_cast<const float2*>(qr0 + c0 + 8));
            const float2 f3 = __ldcs(reinterpret_cast<const float2*>(qr8 + c0 + 8));
            tsplit2(fmap(f0.x), fmap(f0.y), qa[0][kt][0], qa[1][kt][0]);
            tsplit2(fmap(f1.x), fmap(f1.y), qa[0][kt][1], qa[1][kt][1]);
            tsplit2(fmap(f2.x), fmap(f2.y), qa[0][kt][2], qa[1][kt][2]);
            tsplit2(fmap(f3.x), fmap(f3.y), qa[0][kt][3], qa[1][kt][3]);
        }
    }

    // ---- P0: load k,v chunk (streaming); fmap(k); trunc-split -> smem tiles.
    //      Ksum partials accumulate in registers (each thread's d4 is fixed).
    float ksp[4] = {0.f, 0.f, 0.f, 0.f};
#pragma unroll 4
    for (int it = 0; it < 8; it++) {
        const int i = tid + it * 256;
        const int l = i >> 4, d4 = (i & 15) * 4;
        const long g = gbase + (long)l * HD_ + d4;
        const int so = (l * PS_ + d4) * 2;
        uint2 hi, lo;

        const float4 kv = __ldcs(reinterpret_cast<const float4*>(&k[g]));
        const float4 vv = __ldcs(reinterpret_cast<const float4*>(&v[g]));

        float fk[4] = {fmap(kv.x), fmap(kv.y), fmap(kv.z), fmap(kv.w)};
        ksp[0] += fk[0]; ksp[1] += fk[1]; ksp[2] += fk[2]; ksp[3] += fk[3];
        tsplit4(fk, hi, lo);
        *reinterpret_cast<uint2*>(smem + OFF_KH + so) = hi;
        *reinterpret_cast<uint2*>(smem + OFF_KL + so) = lo;

        float fv[4] = {vv.x, vv.y, vv.z, vv.w};
        tsplit4(fv, hi, lo);
        *reinterpret_cast<uint2*>(smem + OFF_VH + so) = hi;
        *reinterpret_cast<uint2*>(smem + OFF_VL + so) = lo;
    }
    {   // park Ksum partials: red[t][d], t = tid>>4 (l-group), d = (tid&15)*4
        float* red = reinterpret_cast<float*>(smem + OFF_RED);
        *reinterpret_cast<float4*>(&red[(tid >> 4) * 64 + (tid & 15) * 4]) =
            make_float4(ksp[0], ksp[1], ksp[2], ksp[3]);
    }
    __syncthreads();

    const int krow = (lane & 7) + ((lane >> 4) & 1) * 8;   // K x4 (phase A)
    const int kcol = ((lane >> 3) & 1) * 8;
    const int vrow = (lane & 7) + ((lane >> 3) & 1) * 8;   // V/S x4t + x2t row
    const int vcol = ((lane >> 4) & 1) * 8;
    const int asrow = (lane & 7) + ((lane >> 4) & 1) * 8;  // K x4t (aggregate MMA)
    const int ascol = ((lane >> 3) & 1) * 8;

    const int m0r = r0 + g4, m1r = m0r + 8;
    float z0 = 0.f, z1 = 0.f;
    float o[8][4];
#pragma unroll
    for (int nt = 0; nt < 8; nt++)
#pragma unroll
        for (int t = 0; t < 4; t++) o[nt][t] = 0.f;

    // ---- section: chunk KV aggregate + Ksum finish + publish (DEAD last chunk)
    auto do_agg = [&]() {
        if (c >= NC_ - 1) return;
        float acc[4][4];
#pragma unroll
        for (int mt = 0; mt < 4; mt++)
#pragma unroll
            for (int t = 0; t < 4; t++) acc[mt][t] = 0.f;

#pragma unroll
        for (int kt = 0; kt < 8; kt++) {
            uint32_t bh0, bh1, bl0, bl1;
            const uint32_t adrV = sb + OFF_VH + (uint32_t)(((kt * 16 + vrow) * PS_ + wid * 8) * 2);
            ldsm_x2t(bh0, bh1, adrV);
            ldsm_x2t(bl0, bl1, adrV + (OFF_VL - OFF_VH));
#pragma unroll
            for (int mt = 0; mt < 4; mt++) {
                uint32_t ah[4], al[4];
                const uint32_t adrK = sb + OFF_KH +
                    (uint32_t)(((kt * 16 + asrow) * PS_ + mt * 16 + ascol) * 2);
                ldsm_x4t(ah, adrK);
                ldsm_x4t(al, adrK + (OFF_KL - OFF_KH));
                mma16816(acc[mt], ah, bh0, bh1);
                mma16816(acc[mt], ah, bl0, bl1);
                mma16816(acc[mt], al, bh0, bh1);
            }
        }

        const int m = wid * 8 + 2 * t4;
#pragma unroll
        for (int mt = 0; mt < 4; mt++) {
            const int d0 = mt * 16 + g4;
            *reinterpret_cast<float2*>(&g_agg[blk][d0 * M_ + m]) =
                make_float2(acc[mt][0], acc[mt][1]);
            *reinterpret_cast<float2*>(&g_agg[blk][(d0 + 8) * M_ + m]) =
                make_float2(acc[mt][2], acc[mt][3]);
        }

        // Ksum finish: sum the 16 P0 partials per d (conflict-free LDS)
        if (tid < 64) {
            const float* red = reinterpret_cast<const float*>(smem + OFF_RED);
            float s = 0.f;
#pragma unroll
            for (int t = 0; t < 16; t++) s += red[t * 64 + tid];
            g_agg[blk][D_ * M_ + tid] = s;
        }
        __syncthreads();
        if (tid == 0) st_release(&g_flag[blk], (c == 0) ? 3 : 1);
    };

    // ---- section: fused phase A+B (intra-chunk) ------------------------------
    auto do_ab = [&]() {
        for (int j2 = 0; j2 <= rt; j2++) {
            float acch[2][4] = {{0.f, 0.f, 0.f, 0.f}, {0.f, 0.f, 0.f, 0.f}};
            float accl[2][4] = {{0.f, 0.f, 0.f, 0.f}, {0.f, 0.f, 0.f, 0.f}};
#pragma unroll
            for (int kt = 0; kt < 4; kt++) {
                uint32_t kh[4], kl[4];
                const uint32_t adr = sb + OFF_KH +
                    (uint32_t)(((16 * j2 + krow) * PS_ + kt * 16 + kcol) * 2);
                ldsm_x4(kh, adr);
                ldsm_x4(kl, adr + (OFF_KL - OFF_KH));
                mma16816(acch[0], qa[0][kt], kh[0], kh[1]);
                mma16816(acch[1], qa[0][kt], kh[2], kh[3]);
                mma16816(accl[0], qa[0][kt], kl[0], kl[1]);
                mma16816(accl[1], qa[0][kt], kl[2], kl[3]);
                mma16816(accl[0], qa[1][kt], kh[0], kh[1]);
                mma16816(accl[1], qa[1][kt], kh[2], kh[3]);
            }

            // R16: prefetch V fragments for nt2=0 BEFORE the conversion block —
            // their LDS latency hides under the mask/rowsum/split ALU work.
            uint32_t vh[4], vl[4];
            {
                const uint32_t adr0 = sb + OFF_VH +
                    (uint32_t)(((16 * j2 + vrow) * PS_ + vcol) * 2);
                ldsm_x4t(vh, adr0);
                ldsm_x4t(vl, adr0 + (OFF_VL - OFF_VH));
            }

            uint32_t aH[4], aL[4];
#pragma unroll
            for (int tl = 0; tl < 2; tl++) {
                float c0 = acch[tl][0] + accl[tl][0];
                float c1 = acch[tl][1] + accl[tl][1];
                float c2 = acch[tl][2] + accl[tl][2];
                float c3 = acch[tl][3] + accl[tl][3];
                if (j2 == rt) {
                    const int n0 = 16 * rt + tl * 8 + 2 * t4;
                    c0 = (n0     <= m0r) ? c0 : 0.f;
                    c1 = (n0 + 1 <= m0r) ? c1 : 0.f;
                    c2 = (n0     <= m1r) ? c2 : 0.f;
                    c3 = (n0 + 1 <= m1r) ? c3 : 0.f;
                }
                z0 += c0 + c1;
                z1 += c2 + c3;
                tsplit2(c0, c1, aH[tl * 2], aL[tl * 2]);
                tsplit2(c2, c3, aH[tl * 2 + 1], aL[tl * 2 + 1]);
            }

#pragma unroll
            for (int nt2 = 0; nt2 < 4; nt2++) {
                if (nt2 > 0) {
                    const uint32_t adr = sb + OFF_VH +
                        (uint32_t)(((16 * j2 + vrow) * PS_ + nt2 * 16 + vcol) * 2);
                    ldsm_x4t(vh, adr);
                    ldsm_x4t(vl, adr + (OFF_VL - OFF_VH));
                }
                mma16816(o[2 * nt2],     aH, vh[0], vh[1]);
                mma16816(o[2 * nt2 + 1], aH, vh[2], vh[3]);
                mma16816(o[2 * nt2],     aH, vl[0], vl[1]);
                mma16816(o[2 * nt2 + 1], aH, vl[2], vl[3]);
                mma16816(o[2 * nt2],     aL, vh[0], vh[1]);
                mma16816(o[2 * nt2 + 1], aL, vh[2], vh[3]);
            }
        }
        z0 += __shfl_xor_sync(0xffffffffu, z0, 1);
        z0 += __shfl_xor_sync(0xffffffffu, z0, 2);
        z1 += __shfl_xor_sync(0xffffffffu, z1, 1);
        z1 += __shfl_xor_sync(0xffffffffu, z1, 2);
    };

    // ---- de-phase co-resident blocks: order sections by block parity --------
    if ((blk >> 2) & 1) {
        do_ab();
        do_agg();
    } else {
        do_agg();
        do_ab();
    }

    // ---- block-wide lookback + phase C (skipped for c == 0) -----------------
    float o9[4] = {0.f, 0.f, 0.f, 0.f};
    if (c > 0) {
        float sp[16];
#pragma unroll
        for (int t = 0; t < 16; t++) sp[t] = 0.f;
        float ksum_prev = 0.f;
        float ksum_own = (c < NC_ - 1 && tid < 64) ? g_agg[blk][D_ * M_ + tid] : 0.f;

        volatile int* stat_s = reinterpret_cast<volatile int*>(smem + OFF_ST);
        int j = blk - BH_;
        while (true) {
            if (tid == 0) {
                int s;
                do { s = ld_acquire(&g_flag[j]); } while (s == 0);
                *stat_s = s;
            }
            __syncthreads();
            const int s = *stat_s;
            const float* src = (s == 2) ? g_inc[j] : g_agg[j];
#pragma unroll
            for (int ii = 0; ii < 4; ii++) {
                const float4 t = *reinterpret_cast<const float4*>(&src[4 * (tid + ii * 256)]);
                sp[ii * 4 + 0] += t.x; sp[ii * 4 + 1] += t.y;
                sp[ii * 4 + 2] += t.z; sp[ii * 4 + 3] += t.w;
            }
            if (tid < 64) ksum_prev += src[D_ * M_ + tid];
            __syncthreads();
            if (s >= 2) break;
            j -= BH_;
        }

        // publish inclusive (exclusive prefix + own aggregate)
        if (c < NC_ - 1) {
#pragma unroll
            for (int ii = 0; ii < 4; ii++) {
                const float4 t = *reinterpret_cast<const float4*>(&g_agg[blk][4 * (tid + ii * 256)]);
                *reinterpret_cast<float4*>(&g_inc[blk][4 * (tid + ii * 256)]) =
                    make_float4(sp[ii * 4 + 0] + t.x, sp[ii * 4 + 1] + t.y,
                                sp[ii * 4 + 2] + t.z, sp[ii * 4 + 3] + t.w);
            }
            if (tid < 64) g_inc[blk][D_ * M_ + tid] = ksum_prev + ksum_own;
            __syncthreads();
            if (tid == 0) st_release(&g_flag[blk], 2);
        } else {
            __syncthreads();
        }

        // split S_prev -> S smem tiles + Ksum column 64
#pragma unroll
        for (int ii = 0; ii < 4; ii++) {
            const int i = tid + ii * 256;
            const int d = i >> 4, m4 = (i & 15) * 4;
            uint2 hi, lo;
            tsplit4(&sp[ii * 4], hi, lo);
            const int so = (d * PS_ + m4) * 2;
            *reinterpret_cast<uint2*>(smem + OFF_SH + so) = hi;
            *reinterpret_cast<uint2*>(smem + OFF_SL + so) = lo;
        }
        if (tid < D_) {
            uint32_t hh, ll;
            tsplit2(ksum_prev, 0.f, hh, ll);
            const int so = (tid * PS_ + 64) * 2;
            *reinterpret_cast<uint2*>(smem + OFF_SH + so) = make_uint2(hh, 0u);
            *reinterpret_cast<uint2*>(smem + OFF_SH + so + 8) = make_uint2(0u, 0u);
            *reinterpret_cast<uint2*>(smem + OFF_SL + so) = make_uint2(ll, 0u);
            *reinterpret_cast<uint2*>(smem + OFF_SL + so + 8) = make_uint2(0u, 0u);
        }
        __syncthreads();

        // phase C: O += Qf S_prev (+ 9th n-tile -> qdk)
#pragma unroll
        for (int kt = 0; kt < 4; kt++) {
#pragma unroll
            for (int nt2 = 0; nt2 < 4; nt2++) {
                uint32_t vh[4], vl[4];
                const uint32_t adr = sb + OFF_SH +
                    (uint32_t)(((kt * 16 + vrow) * PS_ + nt2 * 16 + vcol) * 2);
                ldsm_x4t(vh, adr);
                ldsm_x4t(vl, adr + (OFF_SL - OFF_SH));
                mma16816(o[2 * nt2],     qa[0][kt], vh[0], vh[1]);
                mma16816(o[2 * nt2 + 1], qa[0][kt], vh[2], vh[3]);
                mma16816(o[2 * nt2],     qa[0][kt], vl[0], vl[1]);
                mma16816(o[2 * nt2 + 1], qa[0][kt], vl[2], vl[3]);
                mma16816(o[2 * nt2],     qa[1][kt], vh[0], vh[1]);
                mma16816(o[2 * nt2 + 1], qa[1][kt], vh[2], vh[3]);
            }
            {
                uint32_t bh0, bh1, bl0, bl1;
                const uint32_t adr = sb + OFF_SH +
                    (uint32_t)(((kt * 16 + vrow) * PS_ + 64) * 2);
                ldsm_x2t(bh0, bh1, adr);
                ldsm_x2t(bl0, bl1, adr + (OFF_SL - OFF_SH));
                mma16816(o9, qa[0][kt], bh0, bh1);
                mma16816(o9, qa[0][kt], bl0, bl1);
                mma16816(o9, qa[1][kt], bh0, bh1);
            }
        }
    }

    // ---- epilogue: z = rowsum(A) + Qf.Ksum_prev; divide, store (streaming) --
    {
        const float qdk_a = __shfl_sync(0xffffffffu, o9[0], g4 * 4);
        const float qdk_b = __shfl_sync(0xffffffffu, o9[2], g4 * 4);
        const float inva = 1.f / (z0 + qdk_a + EPS_);
        const float invb = 1.f / (z1 + qdk_b + EPS_);
        const long ob0 = gbase + (long)m0r * HD_;
        const long ob1 = gbase + (long)m1r * HD_;
#pragma unroll
        for (int nt = 0; nt < 8; nt++) {
            const int n = nt * 8 + 2 * t4;
            __stcs(reinterpret_cast<float2*>(&out[ob0 + n]),
                   make_float2(o[nt][0] * inva, o[nt][1] * inva));
            __stcs(reinterpret_cast<float2*>(&out[ob1 + n]),
                   make_float2(o[nt][2] * invb, o[nt][3] * invb));
        }
    }
}

// ---------------------------------------------------------------------------
extern "C" void kernel_launch(void* const* d_in, const int* in_sizes, int n_in,
                              void* d_out, int out_size) {
    const float* q = (const float*)d_in[0];
    const float* k = (const float*)d_in[1];
    const float* v = (const float*)d_in[2];
    float* out = (float*)d_out;

    cudaFuncSetAttribute(la_fused, cudaFuncAttributeMaxDynamicSharedMemorySize, SMEM3);

    la_clear<<<(NBLK_ + 255) / 256, 256>>>();
    la_fused<<<NBLK_, 256, SMEM3>>>(q, k, v, out);
}

// round 17
// speedup vs baseline: 1.1569x; 1.0053x over previous
#include <cuda_runtime.h>
#include <cuda_bf16.h>
#include <cstdint>

// Causal linear attention (elu+1), SINGLE fused kernel (chunk KV aggregate +
// decoupled-lookback prefix + intra-chunk attention), mma.sync bf16 hi/lo.
// q,k,v: [B=4, L=2048, H=16, D=64] fp32 -> out [B,L,H,64] fp32.
// R13: de-phased co-resident blocks. R14: Ksum in P0; no redundant fence.
// R16: V-frag prefetch over the A-conversion block.
// R17: do_agg re-tiled (warp = d-tile x m-half): 80 -> 48 LDSM per warp.

namespace {
constexpr int B_ = 4, L_ = 2048, H_ = 16, D_ = 64, M_ = 64;
constexpr int C_ = 128;
constexpr int NC_ = L_ / C_;   // 16
constexpr int BH_ = B_ * H_;   // 64
constexpr int NBLK_ = BH_ * NC_;  // 1024
constexpr float EPS_ = 1e-6f;
constexpr int HD_ = H_ * D_;   // 1024
constexpr int PS_ = 72;        // padded row stride (bf16) -> 144B, conflict-free LDSM

constexpr int SZT = C_ * PS_ * 2;   // 18432 B per 128-row bf16 tile
constexpr int SZS = 64 * PS_ * 2;   // 9216 B per 64-row bf16 tile

// smem layout (Q never in smem; loaded straight into A-fragments)
constexpr int OFF_KH = 0;
constexpr int OFF_KL = OFF_KH + SZT;
constexpr int OFF_VH = OFF_KL + SZT;
constexpr int OFF_VL = OFF_VH + SZT;          // K/V tiles: 73728 B
constexpr int OFF_SH = 4 * SZT;               // S hi tile (9216B)
constexpr int OFF_SL = OFF_SH + SZS;          // S lo tile (9216B)
constexpr int OFF_RED = OFF_SL + SZS;         // 16x64 fp32 Ksum partials (4KB)
constexpr int OFF_ST  = OFF_RED + 4096;       // lookback status word
constexpr int SMEM3   = OFF_ST + 16;          // ~94 KB -> 2 blocks/SM

constexpr int AGG_N = D_ * M_ + D_;           // 4160 floats: KV + Ksum
}

__device__ float g_agg[NBLK_][AGG_N];
__device__ float g_inc[NBLK_][AGG_N];
__device__ int   g_flag[NBLK_];

__device__ __forceinline__ float fmap(float x) { return x > 0.f ? x + 1.f : __expf(x); }

__device__ __forceinline__ uint32_t smem_u32(const void* p) {
    uint32_t a;
    asm("{ .reg .u64 t; cvta.to.shared.u64 t, %1; cvt.u32.u64 %0, t; }" : "=r"(a) : "l"(p));
    return a;
}
__device__ __forceinline__ int ld_acquire(const int* p) {
    int v;
    asm volatile("ld.acquire.gpu.global.b32 %0, [%1];" : "=r"(v) : "l"(p) : "memory");
    return v;
}
__device__ __forceinline__ void st_release(int* p, int v) {
    asm volatile("st.release.gpu.global.b32 [%0], %1;" :: "l"(p), "r"(v) : "memory");
}
// truncation-based hi/lo split of a float pair -> packed bf16x2 (lo lane = f0)
__device__ __forceinline__ void tsplit2(float f0, float f1, uint32_t& h, uint32_t& l) {
    const uint32_t u0 = __float_as_uint(f0), u1 = __float_as_uint(f1);
    asm("prmt.b32 %0, %1, %2, 0x7632;" : "=r"(h) : "r"(u0), "r"(u1));
    const float r0 = f0 - __uint_as_float(u0 & 0xffff0000u);
    const float r1 = f1 - __uint_as_float(u1 & 0xffff0000u);
    asm("cvt.rn.bf16x2.f32 %0, %1, %2;" : "=r"(l) : "f"(r1), "f"(r0));
}
__device__ __forceinline__ void tsplit4(const float* f, uint2& hi, uint2& lo) {
    tsplit2(f[0], f[1], hi.x, lo.x);
    tsplit2(f[2], f[3], hi.y, lo.y);
}

__device__ __forceinline__ void ldsm_x4(uint32_t* r, uint32_t addr) {
    asm volatile("ldmatrix.sync.aligned.m8n8.x4.shared.b16 {%0,%1,%2,%3}, [%4];"
                 : "=r"(r[0]), "=r"(r[1]), "=r"(r[2]), "=r"(r[3]) : "r"(addr));
}
__device__ __forceinline__ void ldsm_x4t(uint32_t* r, uint32_t addr) {
    asm volatile("ldmatrix.sync.aligned.m8n8.x4.trans.shared.b16 {%0,%1,%2,%3}, [%4];"
                 : "=r"(r[0]), "=r"(r[1]), "=r"(r[2]), "=r"(r[3]) : "r"(addr));
}
__device__ __forceinline__ void ldsm_x2t(uint32_t& b0, uint32_t& b1, uint32_t addr) {
    asm volatile("ldmatrix.sync.aligned.m8n8.x2.trans.shared.b16 {%0,%1}, [%2];"
                 : "=r"(b0), "=r"(b1) : "r"(addr));
}
__device__ __forceinline__ void mma16816(float* c, const uint32_t* a, uint32_t b0, uint32_t b1) {
    asm("mma.sync.aligned.m16n8k16.row.col.f32.bf16.bf16.f32 "
        "{%0,%1,%2,%3}, {%4,%5,%6,%7}, {%8,%9}, {%0,%1,%2,%3};"
        : "+f"(c[0]), "+f"(c[1]), "+f"(c[2]), "+f"(c[3])
        : "r"(a[0]), "r"(a[1]), "r"(a[2]), "r"(a[3]), "r"(b0), "r"(b1));
}

// ---------------------------------------------------------------------------
__global__ void la_clear() {
    const int i = blockIdx.x * 256 + threadIdx.x;
    if (i < NBLK_) g_flag[i] = 0;
}

// ---------------------------------------------------------------------------
// Fused kernel. grid = NBLK_ (blk = c*64 + bh), block = 256 (8 warps).
// ---------------------------------------------------------------------------
__global__ __launch_bounds__(256, 2) void la_fused(const float* __restrict__ q,
                                                   const float* __restrict__ k,
                                                   const float* __restrict__ v,
                                                   float* __restrict__ out) {
    extern __shared__ char smem[];
    const uint32_t sb = smem_u32(smem);
    const int tid = threadIdx.x;
    const int wid = tid >> 5, lane = tid & 31;

    const int blk = blockIdx.x;
    const int c = blk >> 6, bh = blk & 63;
    const int b = bh / H_, h = bh % H_;
    const long gbase = (((long)b * L_ + (long)c * C_) * H_ + h) * D_;

    const int rt = (wid < 4) ? wid : 11 - wid;    // SMSP-balanced row-tile
    const int r0 = rt * 16;
    const int g4 = lane >> 2, t4 = lane & 3;

    // ---- qa frags: direct gmem -> register load of Qf (no smem, streaming) --
    uint32_t qa[2][4][4];
    {
        const float* qr0 = q + gbase + (long)(r0 + g4) * HD_;
        const float* qr8 = qr0 + 8 * HD_;
#pragma unroll
        for (int kt = 0; kt < 4; kt++) {
            const int c0 = kt * 16 + 2 * t4;
            const float2 f0 = __ldcs(reinterpret_cast<const float2*>(qr0 + c0));
            const float2 f1 = __ldcs(reinterpret_cast<const float2*>(qr8 + c0));
            const float2 f2 = __ldcs(reinterpret_cast<const float2*>(qr0 + c0 + 8));
            const float2 f3 = __ldcs(reinterpret_cast<const float2*>(qr8 + c0 + 8));
            tsplit2(fmap(f0.x), fmap(f0.y), qa[0][kt][0], qa[1][kt][0]);
            tsplit2(fmap(f1.x), fmap(f1.y), qa[0][kt][1], qa[1][kt][1]);
            tsplit2(fmap(f2.x), fmap(f2.y), qa[0][kt][2], qa[1][kt][2]);
            tsplit2(fmap(f3.x), fmap(f3.y), qa[0][kt][3], qa[1][kt][3]);
        }
    }

    // ---- P0: load k,v chunk (streaming); fmap(k); trunc-split -> smem tiles.
    //      Ksum partials accumulate in registers (each thread's d4 is fixed).
    float ksp[4] = {0.f, 0.f, 0.f, 0.f};
#pragma unroll 4
    for (int it = 0; it < 8; it++) {
        const int i = tid + it * 256;
        const int l = i >> 4, d4 = (i & 15) * 4;
        const long g = gbase + (long)l * HD_ + d4;
        const int so = (l * PS_ + d4) * 2;
        uint2 hi, lo;

        const float4 kv = __ldcs(reinterpret_cast<const float4*>(&k[g]));
        const float4 vv = __ldcs(reinterpret_cast<const float4*>(&v[g]));

        float fk[4] = {fmap(kv.x), fmap(kv.y), fmap(kv.z), fmap(kv.w)};
        ksp[0] += fk[0]; ksp[1] += fk[1]; ksp[2] += fk[2]; ksp[3] += fk[3];
        tsplit4(fk, hi, lo);
        *reinterpret_cast<uint2*>(smem + OFF_KH + so) = hi;
        *reinterpret_cast<uint2*>(smem + OFF_KL + so) = lo;

        float fv[4] = {vv.x, vv.y, vv.z, vv.w};
        tsplit4(fv, hi, lo);
        *reinterpret_cast<uint2*>(smem + OFF_VH + so) = hi;
        *reinterpret_cast<uint2*>(smem + OFF_VL + so) = lo;
    }
    {   // park Ksum partials: red[t][d], t = tid>>4 (l-group), d = (tid&15)*4
        float* red = reinterpret_cast<float*>(smem + OFF_RED);
        *reinterpret_cast<float4*>(&red[(tid >> 4) * 64 + (tid & 15) * 4]) =
            make_float4(ksp[0], ksp[1], ksp[2], ksp[3]);
    }
    __syncthreads();

    const int krow = (lane & 7) + ((lane >> 4) & 1) * 8;   // K x4 (phase A)
    const int kcol = ((lane >> 3) & 1) * 8;
    const int vrow = (lane & 7) + ((lane >> 3) & 1) * 8;   // V/S x4t + x2t row
    const int vcol = ((lane >> 4) & 1) * 8;
    const int asrow = (lane & 7) + ((lane >> 4) & 1) * 8;  // K x4t (aggregate MMA)
    const int ascol = ((lane >> 3) & 1) * 8;

    const int m0r = r0 + g4, m1r = m0r + 8;
    float z0 = 0.f, z1 = 0.f;
    float o[8][4];
#pragma unroll
    for (int nt = 0; nt < 8; nt++)
#pragma unroll
        for (int t = 0; t < 4; t++) o[nt][t] = 0.f;

    // ---- section: chunk KV aggregate + Ksum finish + publish (DEAD last chunk)
    // R17 tiling: warp w owns d-tile mt = w&3 (16 rows) and m-half nh=(w>>2)*32.
    auto do_agg = [&]() {
        if (c >= NC_ - 1) return;
        const int mt = wid & 3;
        const int nh = (wid >> 2) * 32;
        float acc[4][4];
#pragma unroll
        for (int nt = 0; nt < 4; nt++)
#pragma unroll
            for (int t = 0; t < 4; t++) acc[nt][t] = 0.f;

#pragma unroll
        for (int kt = 0; kt < 8; kt++) {
            uint32_t ah[4], al[4];
            const uint32_t adrK = sb + OFF_KH +
                (uint32_t)(((kt * 16 + asrow) * PS_ + mt * 16 + ascol) * 2);
            ldsm_x4t(ah, adrK);
            ldsm_x4t(al, adrK + (OFF_KL - OFF_KH));
#pragma unroll
            for (int v2 = 0; v2 < 2; v2++) {
                uint32_t vh[4], vl[4];
                const uint32_t adrV = sb + OFF_VH +
                    (uint32_t)(((kt * 16 + vrow) * PS_ + nh + v2 * 16 + vcol) * 2);
                ldsm_x4t(vh, adrV);
                ldsm_x4t(vl, adrV + (OFF_VL - OFF_VH));
                mma16816(acc[2 * v2],     ah, vh[0], vh[1]);
                mma16816(acc[2 * v2 + 1], ah, vh[2], vh[3]);
                mma16816(acc[2 * v2],     ah, vl[0], vl[1]);
                mma16816(acc[2 * v2 + 1], ah, vl[2], vl[3]);
                mma16816(acc[2 * v2],     al, vh[0], vh[1]);
                mma16816(acc[2 * v2 + 1], al, vh[2], vh[3]);
            }
        }

        // write aggregate KV: rows mt*16+g4(+8), cols nh + nt*8 + 2*t4
        const int d0 = mt * 16 + g4;
#pragma unroll
        for (int nt = 0; nt < 4; nt++) {
            const int m = nh + nt * 8 + 2 * t4;
            *reinterpret_cast<float2*>(&g_agg[blk][d0 * M_ + m]) =
                make_float2(acc[nt][0], acc[nt][1]);
            *reinterpret_cast<float2*>(&g_agg[blk][(d0 + 8) * M_ + m]) =
                make_float2(acc[nt][2], acc[nt][3]);
        }

        // Ksum finish: sum the 16 P0 partials per d (conflict-free LDS)
        if (tid < 64) {
            const float* red = reinterpret_cast<const float*>(smem + OFF_RED);
            float s = 0.f;
#pragma unroll
            for (int t = 0; t < 16; t++) s += red[t * 64 + tid];
            g_agg[blk][D_ * M_ + tid] = s;
        }
        __syncthreads();
        if (tid == 0) st_release(&g_flag[blk], (c == 0) ? 3 : 1);
    };

    // ---- section: fused phase A+B (intra-chunk) ------------------------------
    auto do_ab = [&]() {
        for (int j2 = 0; j2 <= rt; j2++) {
            float acch[2][4] = {{0.f, 0.f, 0.f, 0.f}, {0.f, 0.f, 0.f, 0.f}};
            float accl[2][4] = {{0.f, 0.f, 0.f, 0.f}, {0.f, 0.f, 0.f, 0.f}};
#pragma unroll
            for (int kt = 0; kt < 4; kt++) {
                uint32_t kh[4], kl[4];
                const uint32_t adr = sb + OFF_KH +
                    (uint32_t)(((16 * j2 + krow) * PS_ + kt * 16 + kcol) * 2);
                ldsm_x4(kh, adr);
                ldsm_x4(kl, adr + (OFF_KL - OFF_KH));
                mma16816(acch[0], qa[0][kt], kh[0], kh[1]);
                mma16816(acch[1], qa[0][kt], kh[2], kh[3]);
                mma16816(accl[0], qa[0][kt], kl[0], kl[1]);
                mma16816(accl[1], qa[0][kt], kl[2], kl[3]);
                mma16816(accl[0], qa[1][kt], kh[0], kh[1]);
                mma16816(accl[1], qa[1][kt], kh[2], kh[3]);
            }

            // prefetch V fragments for nt2=0 (latency hidden under conversion)
            uint32_t vh[4], vl[4];
            {
                const uint32_t adr0 = sb + OFF_VH +
                    (uint32_t)(((16 * j2 + vrow) * PS_ + vcol) * 2);
                ldsm_x4t(vh, adr0);
                ldsm_x4t(vl, adr0 + (OFF_VL - OFF_VH));
            }

            uint32_t aH[4], aL[4];
#pragma unroll
            for (int tl = 0; tl < 2; tl++) {
                float c0 = acch[tl][0] + accl[tl][0];
                float c1 = acch[tl][1] + accl[tl][1];
                float c2 = acch[tl][2] + accl[tl][2];
                float c3 = acch[tl][3] + accl[tl][3];
                if (j2 == rt) {
                    const int n0 = 16 * rt + tl * 8 + 2 * t4;
                    c0 = (n0     <= m0r) ? c0 : 0.f;
                    c1 = (n0 + 1 <= m0r) ? c1 : 0.f;
                    c2 = (n0     <= m1r) ? c2 : 0.f;
                    c3 = (n0 + 1 <= m1r) ? c3 : 0.f;
                }
                z0 += c0 + c1;
                z1 += c2 + c3;
                tsplit2(c0, c1, aH[tl * 2], aL[tl * 2]);
                tsplit2(c2, c3, aH[tl * 2 + 1], aL[tl * 2 + 1]);
            }

#pragma unroll
            for (int nt2 = 0; nt2 < 4; nt2++) {
                if (nt2 > 0) {
                    const uint32_t adr = sb + OFF_VH +
                        (uint32_t)(((16 * j2 + vrow) * PS_ + nt2 * 16 + vcol) * 2);
                    ldsm_x4t(vh, adr);
                    ldsm_x4t(vl, adr + (OFF_VL - OFF_VH));
                }
                mma16816(o[2 * nt2],     aH, vh[0], vh[1]);
                mma16816(o[2 * nt2 + 1], aH, vh[2], vh[3]);
                mma16816(o[2 * nt2],     aH, vl[0], vl[1]);
                mma16816(o[2 * nt2 + 1], aH, vl[2], vl[3]);
                mma16816(o[2 * nt2],     aL, vh[0], vh[1]);
                mma16816(o[2 * nt2 + 1], aL, vh[2], vh[3]);
            }
        }
        z0 += __shfl_xor_sync(0xffffffffu, z0, 1);
        z0 += __shfl_xor_sync(0xffffffffu, z0, 2);
        z1 += __shfl_xor_sync(0xffffffffu, z1, 1);
        z1 += __shfl_xor_sync(0xffffffffu, z1, 2);
    };

    // ---- de-phase co-resident blocks: order sections by block parity --------
    if ((blk >> 2) & 1) {
        do_ab();
        do_agg();
    } else {
        do_agg();
        do_ab();
    }

    // ---- block-wide lookback + phase C (skipped for c == 0) -----------------
    float o9[4] = {0.f, 0.f, 0.f, 0.f};
    if (c > 0) {
        float sp[16];
#pragma unroll
        for (int t = 0; t < 16; t++) sp[t] = 0.f;
        float ksum_prev = 0.f;
        float ksum_own = (c < NC_ - 1 && tid < 64) ? g_agg[blk][D_ * M_ + tid] : 0.f;

        volatile int* stat_s = reinterpret_cast<volatile int*>(smem + OFF_ST);
        int j = blk - BH_;
        while (true) {
            if (tid == 0) {
                int s;
                do { s = ld_acquire(&g_flag[j]); } while (s == 0);
                *stat_s = s;
            }
            __syncthreads();
            const int s = *stat_s;
            const float* src = (s == 2) ? g_inc[j] : g_agg[j];
#pragma unroll
            for (int ii = 0; ii < 4; ii++) {
                const float4 t = *reinterpret_cast<const float4*>(&src[4 * (tid + ii * 256)]);
                sp[ii * 4 + 0] += t.x; sp[ii * 4 + 1] += t.y;
                sp[ii * 4 + 2] += t.z; sp[ii * 4 + 3] += t.w;
            }
            if (tid < 64) ksum_prev += src[D_ * M_ + tid];
            __syncthreads();
            if (s >= 2) break;
            j -= BH_;
        }

        // publish inclusive (exclusive prefix + own aggregate)
        if (c < NC_ - 1) {
#pragma unroll
            for (int ii = 0; ii < 4; ii++) {
                const float4 t = *reinterpret_cast<const float4*>(&g_agg[blk][4 * (tid + ii * 256)]);
                *reinterpret_cast<float4*>(&g_inc[blk][4 * (tid + ii * 256)]) =
                    make_float4(sp[ii * 4 + 0] + t.x, sp[ii * 4 + 1] + t.y,
                                sp[ii * 4 + 2] + t.z, sp[ii * 4 + 3] + t.w);
            }
            if (tid < 64) g_inc[blk][D_ * M_ + tid] = ksum_prev + ksum_own;
            __syncthreads();
            if (tid == 0) st_release(&g_flag[blk], 2);
        } else {
            __syncthreads();
        }

        // split S_prev -> S smem tiles + Ksum column 64
#pragma unroll
        for (int ii = 0; ii < 4; ii++) {
            const int i = tid + ii * 256;
            const int d = i >> 4, m4 = (i & 15) * 4;
            uint2 hi, lo;
            tsplit4(&sp[ii * 4], hi, lo);
            const int so = (d * PS_ + m4) * 2;
            *reinterpret_cast<uint2*>(smem + OFF_SH + so) = hi;
            *reinterpret_cast<uint2*>(smem + OFF_SL + so) = lo;
        }
        if (tid < D_) {
            uint32_t hh, ll;
            tsplit2(ksum_prev, 0.f, hh, ll);
            const int so = (tid * PS_ + 64) * 2;
            *reinterpret_cast<uint2*>(smem + OFF_SH + so) = make_uint2(hh, 0u);
            *reinterpret_cast<uint2*>(smem + OFF_SH + so + 8) = make_uint2(0u, 0u);
            *reinterpret_cast<uint2*>(smem + OFF_SL + so) = make_uint2(ll, 0u);
            *reinterpret_cast<uint2*>(smem + OFF_SL + so + 8) = make_uint2(0u, 0u);
        }
        __syncthreads();

        // phase C: O += Qf S_prev (+ 9th n-tile -> qdk)
#pragma unroll
        for (int kt = 0; kt < 4; kt++) {
#pragma unroll
            for (int nt2 = 0; nt2 < 4; nt2++) {
                uint32_t vh[4], vl[4];
                const uint32_t adr = sb + OFF_SH +
                    (uint32_t)(((kt * 16 + vrow) * PS_ + nt2 * 16 + vcol) * 2);
                ldsm_x4t(vh, adr);
                ldsm_x4t(vl, adr + (OFF_SL - OFF_SH));
                mma16816(o[2 * nt2],     qa[0][kt], vh[0], vh[1]);
                mma16816(o[2 * nt2 + 1], qa[0][kt], vh[2], vh[3]);
                mma16816(o[2 * nt2],     qa[0][kt], vl[0], vl[1]);
                mma16816(o[2 * nt2 + 1], qa[0][kt], vl[2], vl[3]);
                mma16816(o[2 * nt2],     qa[1][kt], vh[0], vh[1]);
                mma16816(o[2 * nt2 + 1], qa[1][kt], vh[2], vh[3]);
            }
            {
                uint32_t bh0, bh1, bl0, bl1;
                const uint32_t adr = sb + OFF_SH +
                    (uint32_t)(((kt * 16 + vrow) * PS_ + 64) * 2);
                ldsm_x2t(bh0, bh1, adr);
                ldsm_x2t(bl0, bl1, adr + (OFF_SL - OFF_SH));
                mma16816(o9, qa[0][kt], bh0, bh1);
                mma16816(o9, qa[0][kt], bl0, bl1);
                mma16816(o9, qa[1][kt], bh0, bh1);
            }
        }
    }

    // ---- epilogue: z = rowsum(A) + Qf.Ksum_prev; divide, store (streaming) --
    {
        const float qdk_a = __shfl_sync(0xffffffffu, o9[0], g4 * 4);
        const float qdk_b = __shfl_sync(0xffffffffu, o9[2], g4 * 4);
        const float inva = 1.f / (z0 + qdk_a + EPS_);
        const float invb = 1.f / (z1 + qdk_b + EPS_);
        const long ob0 = gbase + (long)m0r * HD_;
        const long ob1 = gbase + (long)m1r * HD_;
#pragma unroll
        for (int nt = 0; nt < 8; nt++) {
            const int n = nt * 8 + 2 * t4;
            __stcs(reinterpret_cast<float2*>(&out[ob0 + n]),
                   make_float2(o[nt][0] * inva, o[nt][1] * inva));
            __stcs(reinterpret_cast<float2*>(&out[ob1 + n]),
                   make_float2(o[nt][2] * invb, o[nt][3] * invb));
        }
    }
}

// ---------------------------------------------------------------------------
extern "C" void kernel_launch(void* const* d_in, const int* in_sizes, int n_in,
                              void* d_out, int out_size) {
    const float* q = (const float*)d_in[0];
    const float* k = (const float*)d_in[1];
    const float* v = (const float*)d_in[2];
    float* out = (float*)d_out;

    cudaFuncSetAttribute(la_fused, cudaFuncAttributeMaxDynamicSharedMemorySize, SMEM3);

    la_clear<<<(NBLK_ + 255) / 256, 256>>>();
    la_fused<<<NBLK_, 256, SMEM3>>>(q, k, v, out);
}